// round 9
// baseline (speedup 1.0000x reference)
#include <cuda_runtime.h>
#include <cuda_bf16.h>
#include <math.h>
#include <stdint.h>

// Problem constants
#define BB 2
#define TT 2048
#define DM 2048
#define NH 32
#define NKV 8
#define HD 64
#define MROWS (BB*TT)          // 4096
#define QN (NH*HD)             // 2048
#define KN (NKV*HD)            // 512
#define GK DM                  // K dim of every GEMM = 2048

// Scratch (device globals — allocation-free)
__device__ float g_q[MROWS*QN];
__device__ float g_k[MROWS*KN];
__device__ float g_v[MROWS*KN];
__device__ float g_att[MROWS*QN];
__device__ float g_xc[MROWS*DM];
__device__ float g_wqc[QN*DM];
__device__ float g_wkc[KN*DM];
__device__ float g_wvc[KN*DM];
__device__ float g_woc[DM*QN];

__device__ __forceinline__ float rna(float x) {
    uint32_t u;
    asm("cvt.rna.tf32.f32 %0, %1;" : "=r"(u) : "f"(x));
    return __uint_as_float(u);
}
__device__ __forceinline__ uint32_t smem_u32(const void* p) {
    uint32_t a;
    asm("{ .reg .u64 t; cvta.to.shared.u64 t, %1; cvt.u32.u64 %0, t; }"
        : "=r"(a) : "l"(p));
    return a;
}
__device__ __forceinline__ void mma_tf32(float c[4], const uint32_t a[4],
                                         const uint32_t b[2]) {
    asm volatile(
        "mma.sync.aligned.m16n8k8.row.col.f32.tf32.tf32.f32 "
        "{%0,%1,%2,%3}, {%4,%5,%6,%7}, {%8,%9}, {%0,%1,%2,%3};"
        : "+f"(c[0]), "+f"(c[1]), "+f"(c[2]), "+f"(c[3])
        : "r"(a[0]), "r"(a[1]), "r"(a[2]), "r"(a[3]), "r"(b[0]), "r"(b[1]));
}

// ---------------------------------------------------------------------------
// Fused tf32 rounding pass for all 5 GEMM operands (1 launch)
// ---------------------------------------------------------------------------
#define N4_X  (MROWS*DM/4)
#define N4_WQ (QN*DM/4)
#define N4_WK (KN*DM/4)
#define N4_WV (KN*DM/4)
#define N4_WO (DM*QN/4)
#define N4_ALL (N4_X + N4_WQ + N4_WK + N4_WV + N4_WO)

__global__ void cvt_all(const float* __restrict__ x,  const float* __restrict__ wq,
                        const float* __restrict__ wk, const float* __restrict__ wv,
                        const float* __restrict__ wo,
                        float* __restrict__ xc,  float* __restrict__ wqc,
                        float* __restrict__ wkc, float* __restrict__ wvc,
                        float* __restrict__ woc) {
    int i = blockIdx.x * blockDim.x + threadIdx.x;
    if (i >= N4_ALL) return;
    const float* src; float* dst; int off;
    if (i < N4_X)                          { src = x;  dst = xc;  off = 0; }
    else if (i < N4_X + N4_WQ)             { src = wq; dst = wqc; off = N4_X; }
    else if (i < N4_X + N4_WQ + N4_WK)     { src = wk; dst = wkc; off = N4_X + N4_WQ; }
    else if (i < N4_X + N4_WQ + N4_WK + N4_WV)
                                           { src = wv; dst = wvc; off = N4_X + N4_WQ + N4_WK; }
    else                                   { src = wo; dst = woc; off = N4_X + N4_WQ + N4_WK + N4_WV; }
    int j = i - off;
    float4 v = ((const float4*)src)[j];
    ((float4*)dst)[j] = make_float4(rna(v.x), rna(v.y), rna(v.z), rna(v.w));
}

// ---------------------------------------------------------------------------
// mma.sync tf32 NT GEMM v2: BM=128, BN=128, BK=32, 256 threads, 3-stage
// cp.async, warp tile 32x64 (8 warps as 4m x 2n) -> 64 acc regs/thread,
// 2 CTAs/SM. Segmented-N for fused QKV; rmask: rna-round epilogue per seg.
// ---------------------------------------------------------------------------
#define BM 128
#define BN 128
#define BK 32
#define NCH (GK/BK)                // 64
#define RST 36
#define ATILEB (128*RST*4)         // 18432 B
#define STAGEB (2*ATILEB)          // 36864 B
#define GEMM_SMEM (3*STAGEB)       // 110592 B

__global__ __launch_bounds__(256, 2) void gemm_mma(
    const float* __restrict__ A,
    const float* __restrict__ B0, const float* __restrict__ B1,
    const float* __restrict__ B2,
    float* __restrict__ C0, float* __restrict__ C1, float* __restrict__ C2,
    int nb1, int nb2, int ld0, int rmask) {
    extern __shared__ float sm[];
    const int tid = threadIdx.x;
    const int bm = blockIdx.y * BM;
    const int bn = blockIdx.x * BN;
    const int wid = tid >> 5, lane = tid & 31;
    const int g = lane >> 2, tg = lane & 3;
    const int wm = (wid >> 1) * 32;      // 0,32,64,96
    const int wn = (wid & 1) * 64;       // 0,64

    const float* Bp; float* Cp; int nb, ldc, seg;
    if (bn < nb1)      { Bp = B0; Cp = C0; nb = bn;       ldc = ld0; seg = 0; }
    else if (bn < nb2) { Bp = B1; Cp = C1; nb = bn - nb1; ldc = 512; seg = 1; }
    else               { Bp = B2; Cp = C2; nb = bn - nb2; ldc = 512; seg = 2; }
    const bool rnd = (rmask >> seg) & 1;

    float c[2][8][4];
#pragma unroll
    for (int i = 0; i < 2; i++)
#pragma unroll
        for (int j = 0; j < 8; j++)
#pragma unroll
            for (int q = 0; q < 4; q++) c[i][j][q] = 0.f;

    const uint32_t sb = smem_u32(sm);

    auto load_chunk = [&](int kc, int s) {
        uint32_t base = sb + s * STAGEB;
#pragma unroll
        for (int j = 0; j < 8; j++) {
            int u = tid + j * 256;        // 0..2047
            uint32_t sa;
            const float* gp;
            if (u < 1024) {               // A: 128 rows x 8 float4
                int r = u >> 3, c16 = u & 7;
                sa = base + r * (RST*4) + c16 * 16;
                gp = A + (size_t)(bm + r) * GK + kc * BK + c16 * 4;
            } else {                      // B: 128 rows x 8 float4
                int uu = u - 1024;
                int r = uu >> 3, c16 = uu & 7;
                sa = base + ATILEB + r * (RST*4) + c16 * 16;
                gp = Bp + (size_t)(nb + r) * GK + kc * BK + c16 * 4;
            }
            asm volatile("cp.async.cg.shared.global [%0], [%1], 16;"
                         :: "r"(sa), "l"(gp));
        }
        asm volatile("cp.async.commit_group;" ::: "memory");
    };

    load_chunk(0, 0);
    load_chunk(1, 1);

    for (int t = 0; t < NCH; t++) {
        if (t + 2 < NCH) {
            load_chunk(t + 2, (t + 2) % 3);
            asm volatile("cp.async.wait_group 2;" ::: "memory");
        } else if (t + 1 < NCH) {
            asm volatile("cp.async.wait_group 1;" ::: "memory");
        } else {
            asm volatile("cp.async.wait_group 0;" ::: "memory");
        }
        __syncthreads();

        const float* Ab = sm + (t % 3) * (STAGEB/4);
        const float* Bb = Ab + ATILEB/4;
#pragma unroll
        for (int ks = 0; ks < 4; ks++) {
            const int k0 = ks * 8;
            uint32_t af[2][4], bf[8][2];
#pragma unroll
            for (int tm = 0; tm < 2; tm++) {
                const int m0 = wm + tm * 16;
                af[tm][0] = __float_as_uint(Ab[(m0 + g)     * RST + k0 + tg]);
                af[tm][1] = __float_as_uint(Ab[(m0 + g + 8) * RST + k0 + tg]);
                af[tm][2] = __float_as_uint(Ab[(m0 + g)     * RST + k0 + tg + 4]);
                af[tm][3] = __float_as_uint(Ab[(m0 + g + 8) * RST + k0 + tg + 4]);
            }
#pragma unroll
            for (int tn = 0; tn < 8; tn++) {
                const int n0 = wn + tn * 8;
                bf[tn][0] = __float_as_uint(Bb[(n0 + g) * RST + k0 + tg]);
                bf[tn][1] = __float_as_uint(Bb[(n0 + g) * RST + k0 + tg + 4]);
            }
#pragma unroll
            for (int tm = 0; tm < 2; tm++)
#pragma unroll
                for (int tn = 0; tn < 8; tn++)
                    mma_tf32(c[tm][tn], af[tm], bf[tn]);
        }
        __syncthreads();
    }

#pragma unroll
    for (int tm = 0; tm < 2; tm++) {
        const int row0 = bm + wm + tm * 16 + g;
#pragma unroll
        for (int tn = 0; tn < 8; tn++) {
            const int col = nb + wn + tn * 8 + tg * 2;
            float2 v0 = make_float2(c[tm][tn][0], c[tm][tn][1]);
            float2 v1 = make_float2(c[tm][tn][2], c[tm][tn][3]);
            if (rnd) {
                v0.x = rna(v0.x); v0.y = rna(v0.y);
                v1.x = rna(v1.x); v1.y = rna(v1.y);
            }
            *(float2*)&Cp[(size_t)row0 * ldc + col]       = v0;
            *(float2*)&Cp[(size_t)(row0 + 8) * ldc + col] = v1;
        }
    }
}

// ---------------------------------------------------------------------------
// Fused RoPE for q and k (in-place), writes tf32-rounded values
// ---------------------------------------------------------------------------
#define ROPE_TOT (BB*TT*(NH+NKV)*32)

__global__ void rope_fused(float* __restrict__ q, float* __restrict__ kk,
                           const float* __restrict__ cs, const float* __restrict__ sn) {
    int idx = blockIdx.x * blockDim.x + threadIdx.x;
    if (idx >= ROPE_TOT) return;
    int d  = idx & 31;
    int h  = (idx >> 5) % (NH + NKV);
    int bt = idx / (32 * (NH + NKV));
    int t  = bt & (TT - 1);
    float* row = (h < NH) ? q + (size_t)bt * QN + h * HD
                          : kk + (size_t)bt * KN + (h - NH) * HD;
    float x1 = row[d], x2 = row[d + 32];
    float c1 = cs[t * HD + d],      s1 = sn[t * HD + d];
    float c2 = cs[t * HD + d + 32], s2 = sn[t * HD + d + 32];
    row[d]      = rna(x1 * c1 - x2 * s1);
    row[d + 32] = rna(x2 * c2 + x1 * s2);
}

// ---------------------------------------------------------------------------
// Tensor-core flash attention v4: 256 threads (8 warps x 16 q-rows),
// q-tile 128, kv-tile 64, cp.async double-buffered K/V, 2 CTAs/SM.
// All inputs pre-rounded tf32. Smem: Kb[2][64][68], Vb[2][64][72],
// Ps[128][68] = 106496 B.
// ---------------------------------------------------------------------------
#define KST 68
#define VST 72
#define PST 68
#define ATTN_SMEM ((2*64*KST + 2*64*VST + 128*PST) * 4)

__global__ __launch_bounds__(256, 2) void attn_tc(const float* __restrict__ q,
                                                  const float* __restrict__ k,
                                                  const float* __restrict__ v,
                                                  float* __restrict__ o) {
    const int qt = (int)gridDim.x - 1 - (int)blockIdx.x;   // heavy CTAs first
    const int h  = blockIdx.y;
    const int b  = blockIdx.z;
    const int kvh = h >> 2;
    const int q0 = qt * 128;

    extern __shared__ float sm[];
    float* Kb = sm;                     // 2 x [64][KST]
    float* Vb = Kb + 2 * 64 * KST;      // 2 x [64][VST]
    float* Ps = Vb + 2 * 64 * VST;      // [128][PST] (Q staging, then P)

    const int tid = threadIdx.x;
    const int w = tid >> 5, lane = tid & 31;
    const int g = lane >> 2, tg = lane & 3;
    const int wq0 = w * 16;

    // ---- Stage all 128 Q rows into Ps (pre-rounded by rope) ----
#pragma unroll
    for (int j = 0; j < 8; j++) {
        int i = tid + j * 256;            // 0..2047 float4 units
        int r = i >> 4, c4 = i & 15;
        *(float4*)&Ps[r * PST + c4 * 4] =
            *(const float4*)&q[(size_t)(b * TT + q0 + r) * QN + h * HD + c4 * 4];
    }
    __syncthreads();

    uint32_t qf[8][4];
#pragma unroll
    for (int ks = 0; ks < 8; ks++) {
        const int k0 = ks * 8;
        qf[ks][0] = __float_as_uint(Ps[(wq0 + g)     * PST + k0 + tg]);
        qf[ks][1] = __float_as_uint(Ps[(wq0 + g + 8) * PST + k0 + tg]);
        qf[ks][2] = __float_as_uint(Ps[(wq0 + g)     * PST + k0 + tg + 4]);
        qf[ks][3] = __float_as_uint(Ps[(wq0 + g + 8) * PST + k0 + tg + 4]);
    }

    // cp.async one 64-row K/V tile into stage s
    auto cp_tile = [&](int kt, int s) {
        const float* kbp = k + (size_t)(b * TT + kt * 64) * KN + kvh * HD;
        const float* vbp = v + (size_t)(b * TT + kt * 64) * KN + kvh * HD;
        float* Kd = Kb + s * 64 * KST;
        float* Vd = Vb + s * 64 * VST;
#pragma unroll
        for (int j = 0; j < 8; j++) {
            int u = tid + j * 256;        // 0..2047
            int r = (u >> 4) & 63, c4 = u & 15;
            if (u < 1024) {
                uint32_t sa = smem_u32(&Kd[r * KST + c4 * 4]);
                asm volatile("cp.async.cg.shared.global [%0], [%1], 16;"
                             :: "r"(sa), "l"(kbp + (size_t)r * KN + c4 * 4));
            } else {
                uint32_t sa = smem_u32(&Vd[r * VST + c4 * 4]);
                asm volatile("cp.async.cg.shared.global [%0], [%1], 16;"
                             :: "r"(sa), "l"(vbp + (size_t)r * KN + c4 * 4));
            }
        }
        asm volatile("cp.async.commit_group;" ::: "memory");
    };

    float oacc[8][4];
#pragma unroll
    for (int nt = 0; nt < 8; nt++)
#pragma unroll
        for (int qq = 0; qq < 4; qq++) oacc[nt][qq] = 0.f;
    float m0 = -INFINITY, m1 = -INFINITY, l0 = 0.f, l1 = 0.f;

    const int nkt = 2 * qt + 2;
    cp_tile(0, 0);

    for (int kt = 0; kt < nkt; ++kt) {
        if (kt + 1 < nkt) {
            cp_tile(kt + 1, (kt + 1) & 1);
            asm volatile("cp.async.wait_group 1;" ::: "memory");
        } else {
            asm volatile("cp.async.wait_group 0;" ::: "memory");
        }
        __syncthreads();

        const float* Ks = Kb + (kt & 1) * 64 * KST;
        const float* Vs = Vb + (kt & 1) * 64 * VST;
        const int k0g = kt * 64;

        // ---- S = Q @ K^T ----
        float sc[8][4];
#pragma unroll
        for (int nt = 0; nt < 8; nt++)
#pragma unroll
            for (int qq = 0; qq < 4; qq++) sc[nt][qq] = 0.f;

#pragma unroll
        for (int ks = 0; ks < 8; ks++) {
            const int k0 = ks * 8;
            uint32_t bf[8][2];
#pragma unroll
            for (int nt = 0; nt < 8; nt++) {
                bf[nt][0] = __float_as_uint(Ks[(nt * 8 + g) * KST + k0 + tg]);
                bf[nt][1] = __float_as_uint(Ks[(nt * 8 + g) * KST + k0 + tg + 4]);
            }
#pragma unroll
            for (int nt = 0; nt < 8; nt++)
                mma_tf32(sc[nt], qf[ks], bf[nt]);
        }

        // ---- scale + causal mask ----
        const float scale = 0.125f;
        if (kt >= 2 * qt) {               // diagonal region
            const int r0 = q0 + wq0 + g, r1 = r0 + 8;
#pragma unroll
            for (int nt = 0; nt < 8; nt++) {
                int c0 = k0g + nt * 8 + 2 * tg, c1 = c0 + 1;
                sc[nt][0] = (c0 <= r0) ? sc[nt][0] * scale : -1e30f;
                sc[nt][1] = (c1 <= r0) ? sc[nt][1] * scale : -1e30f;
                sc[nt][2] = (c0 <= r1) ? sc[nt][2] * scale : -1e30f;
                sc[nt][3] = (c1 <= r1) ? sc[nt][3] * scale : -1e30f;
            }
        } else {
#pragma unroll
            for (int nt = 0; nt < 8; nt++)
#pragma unroll
                for (int qq = 0; qq < 4; qq++) sc[nt][qq] *= scale;
        }

        // ---- online softmax (rows g and g+8; reduce over tg lanes) ----
        float mx0 = -INFINITY, mx1 = -INFINITY;
#pragma unroll
        for (int nt = 0; nt < 8; nt++) {
            mx0 = fmaxf(mx0, fmaxf(sc[nt][0], sc[nt][1]));
            mx1 = fmaxf(mx1, fmaxf(sc[nt][2], sc[nt][3]));
        }
        mx0 = fmaxf(mx0, __shfl_xor_sync(0xffffffffu, mx0, 1));
        mx0 = fmaxf(mx0, __shfl_xor_sync(0xffffffffu, mx0, 2));
        mx1 = fmaxf(mx1, __shfl_xor_sync(0xffffffffu, mx1, 1));
        mx1 = fmaxf(mx1, __shfl_xor_sync(0xffffffffu, mx1, 2));

        float mn0 = fmaxf(m0, mx0), mn1 = fmaxf(m1, mx1);
        float al0 = __expf(m0 - mn0), al1 = __expf(m1 - mn1);
        m0 = mn0; m1 = mn1;
        float rs0 = 0.f, rs1 = 0.f;
#pragma unroll
        for (int nt = 0; nt < 8; nt++) {
            sc[nt][0] = __expf(sc[nt][0] - mn0);
            sc[nt][1] = __expf(sc[nt][1] - mn0);
            sc[nt][2] = __expf(sc[nt][2] - mn1);
            sc[nt][3] = __expf(sc[nt][3] - mn1);
            rs0 += sc[nt][0] + sc[nt][1];
            rs1 += sc[nt][2] + sc[nt][3];
        }
        rs0 += __shfl_xor_sync(0xffffffffu, rs0, 1);
        rs0 += __shfl_xor_sync(0xffffffffu, rs0, 2);
        rs1 += __shfl_xor_sync(0xffffffffu, rs1, 1);
        rs1 += __shfl_xor_sync(0xffffffffu, rs1, 2);
        l0 = l0 * al0 + rs0;
        l1 = l1 * al1 + rs1;
#pragma unroll
        for (int nt = 0; nt < 8; nt++) {
            oacc[nt][0] *= al0; oacc[nt][1] *= al0;
            oacc[nt][2] *= al1; oacc[nt][3] *= al1;
        }

        // ---- P to smem (warp-private rows), reload as A-frags ----
#pragma unroll
        for (int nt = 0; nt < 8; nt++) {
            *(float2*)&Ps[(wq0 + g)     * PST + nt * 8 + 2 * tg] =
                make_float2(sc[nt][0], sc[nt][1]);
            *(float2*)&Ps[(wq0 + g + 8) * PST + nt * 8 + 2 * tg] =
                make_float2(sc[nt][2], sc[nt][3]);
        }
        __syncwarp();

        // ---- O += P @ V ----
#pragma unroll
        for (int ks = 0; ks < 8; ks++) {
            const int kk = ks * 8;
            uint32_t af[4];
            af[0] = __float_as_uint(Ps[(wq0 + g)     * PST + kk + tg]);
            af[1] = __float_as_uint(Ps[(wq0 + g + 8) * PST + kk + tg]);
            af[2] = __float_as_uint(Ps[(wq0 + g)     * PST + kk + tg + 4]);
            af[3] = __float_as_uint(Ps[(wq0 + g + 8) * PST + kk + tg + 4]);
            uint32_t bf[8][2];
#pragma unroll
            for (int nt = 0; nt < 8; nt++) {
                bf[nt][0] = __float_as_uint(Vs[(kk + tg)     * VST + nt * 8 + g]);
                bf[nt][1] = __float_as_uint(Vs[(kk + tg + 4) * VST + nt * 8 + g]);
            }
#pragma unroll
            for (int nt = 0; nt < 8; nt++)
                mma_tf32(oacc[nt], af, bf[nt]);
        }
        __syncthreads();   // all warps done with this K/V buffer
    }

    // ---- normalize + write (tf32-rounded: feeds O-proj GEMM directly) ----
    const float inv0 = 1.f / l0, inv1 = 1.f / l1;
    const int rb = b * TT + q0 + wq0 + g;
#pragma unroll
    for (int nt = 0; nt < 8; nt++) {
        const int col = h * HD + nt * 8 + 2 * tg;
        *(float2*)&o[(size_t)rb * QN + col] =
            make_float2(rna(oacc[nt][0] * inv0), rna(oacc[nt][1] * inv0));
        *(float2*)&o[(size_t)(rb + 8) * QN + col] =
            make_float2(rna(oacc[nt][2] * inv1), rna(oacc[nt][3] * inv1));
    }
}

// ---------------------------------------------------------------------------
// Launcher
// ---------------------------------------------------------------------------
extern "C" void kernel_launch(void* const* d_in, const int* in_sizes, int n_in,
                              void* d_out, int out_size) {
    const float* x   = (const float*)d_in[0];
    const float* cs  = (const float*)d_in[1];
    const float* sn  = (const float*)d_in[2];
    const float* Wq  = (const float*)d_in[3];
    const float* Wk  = (const float*)d_in[4];
    const float* Wv  = (const float*)d_in[5];
    const float* Wo  = (const float*)d_in[6];
    float* out = (float*)d_out;

    float *q_ptr, *k_ptr, *v_ptr, *att_ptr;
    float *xc, *wqc, *wkc, *wvc, *woc;
    cudaGetSymbolAddress((void**)&q_ptr,  g_q);
    cudaGetSymbolAddress((void**)&k_ptr,  g_k);
    cudaGetSymbolAddress((void**)&v_ptr,  g_v);
    cudaGetSymbolAddress((void**)&att_ptr, g_att);
    cudaGetSymbolAddress((void**)&xc,   g_xc);
    cudaGetSymbolAddress((void**)&wqc,  g_wqc);
    cudaGetSymbolAddress((void**)&wkc,  g_wkc);
    cudaGetSymbolAddress((void**)&wvc,  g_wvc);
    cudaGetSymbolAddress((void**)&woc,  g_woc);

    cudaFuncSetAttribute(gemm_mma, cudaFuncAttributeMaxDynamicSharedMemorySize, GEMM_SMEM);
    cudaFuncSetAttribute(attn_tc,  cudaFuncAttributeMaxDynamicSharedMemorySize, ATTN_SMEM);

    // 1) Pre-round all GEMM operands (single launch)
    cvt_all<<<(N4_ALL + 255) / 256, 256>>>(x, Wq, Wk, Wv, Wo,
                                           xc, wqc, wkc, wvc, woc);

    // 2) Fused QKV projection: N = 2048 + 512 + 512; round V segment (bit 2)
    gemm_mma<<<dim3(3072/BN, MROWS/BM), 256, GEMM_SMEM>>>(
        xc, wqc, wkc, wvc, q_ptr, k_ptr, v_ptr, 2048, 2560, QN, 0b100);

    // 3) Fused RoPE on q and k (writes tf32-rounded)
    rope_fused<<<(ROPE_TOT + 255) / 256, 256>>>(q_ptr, k_ptr, cs, sn);

    // 4) Tensor-core flash attention (q-tile 128, 8 warps, double-buffered)
    attn_tc<<<dim3(TT / 128, NH, BB), 256, ATTN_SMEM>>>(q_ptr, k_ptr, v_ptr, att_ptr);

    // 5) Output projection (seg 0 only; no epilogue rounding)
    gemm_mma<<<dim3(DM/BN, MROWS/BM), 256, GEMM_SMEM>>>(
        att_ptr, woc, woc, woc, out, out, out, DM, DM + 512, DM, 0);
}

// round 10
// speedup vs baseline: 1.0036x; 1.0036x over previous
#include <cuda_runtime.h>
#include <cuda_bf16.h>
#include <math.h>
#include <stdint.h>

// Problem constants
#define BB 2
#define TT 2048
#define DM 2048
#define NH 32
#define NKV 8
#define HD 64
#define MROWS (BB*TT)          // 4096
#define QN (NH*HD)             // 2048
#define KN (NKV*HD)            // 512
#define GK DM                  // K dim of every GEMM = 2048

// Scratch (device globals — allocation-free)
__device__ float g_q[MROWS*QN];
__device__ float g_k[MROWS*KN];
__device__ float g_v[MROWS*KN];
__device__ float g_att[MROWS*QN];
__device__ float g_xc[MROWS*DM];
__device__ float g_wqc[QN*DM];
__device__ float g_wkc[KN*DM];
__device__ float g_wvc[KN*DM];
__device__ float g_woc[DM*QN];

__device__ __forceinline__ float rna(float x) {
    uint32_t u;
    asm("cvt.rna.tf32.f32 %0, %1;" : "=r"(u) : "f"(x));
    return __uint_as_float(u);
}
__device__ __forceinline__ uint32_t smem_u32(const void* p) {
    uint32_t a;
    asm("{ .reg .u64 t; cvta.to.shared.u64 t, %1; cvt.u32.u64 %0, t; }"
        : "=r"(a) : "l"(p));
    return a;
}
__device__ __forceinline__ void mma_tf32(float c[4], const uint32_t a[4],
                                         const uint32_t b[2]) {
    asm volatile(
        "mma.sync.aligned.m16n8k8.row.col.f32.tf32.tf32.f32 "
        "{%0,%1,%2,%3}, {%4,%5,%6,%7}, {%8,%9}, {%0,%1,%2,%3};"
        : "+f"(c[0]), "+f"(c[1]), "+f"(c[2]), "+f"(c[3])
        : "r"(a[0]), "r"(a[1]), "r"(a[2]), "r"(a[3]), "r"(b[0]), "r"(b[1]));
}

// ---------------------------------------------------------------------------
// Fused tf32 rounding pass for all 5 GEMM operands (1 launch)
// ---------------------------------------------------------------------------
#define N4_X  (MROWS*DM/4)
#define N4_WQ (QN*DM/4)
#define N4_WK (KN*DM/4)
#define N4_WV (KN*DM/4)
#define N4_WO (DM*QN/4)
#define N4_ALL (N4_X + N4_WQ + N4_WK + N4_WV + N4_WO)

__global__ void cvt_all(const float* __restrict__ x,  const float* __restrict__ wq,
                        const float* __restrict__ wk, const float* __restrict__ wv,
                        const float* __restrict__ wo,
                        float* __restrict__ xc,  float* __restrict__ wqc,
                        float* __restrict__ wkc, float* __restrict__ wvc,
                        float* __restrict__ woc) {
    int i = blockIdx.x * blockDim.x + threadIdx.x;
    if (i >= N4_ALL) return;
    const float* src; float* dst; int off;
    if (i < N4_X)                          { src = x;  dst = xc;  off = 0; }
    else if (i < N4_X + N4_WQ)             { src = wq; dst = wqc; off = N4_X; }
    else if (i < N4_X + N4_WQ + N4_WK)     { src = wk; dst = wkc; off = N4_X + N4_WQ; }
    else if (i < N4_X + N4_WQ + N4_WK + N4_WV)
                                           { src = wv; dst = wvc; off = N4_X + N4_WQ + N4_WK; }
    else                                   { src = wo; dst = woc; off = N4_X + N4_WQ + N4_WK + N4_WV; }
    int j = i - off;
    float4 v = ((const float4*)src)[j];
    ((float4*)dst)[j] = make_float4(rna(v.x), rna(v.y), rna(v.z), rna(v.w));
}

// ---------------------------------------------------------------------------
// mma.sync tf32 NT GEMM v2: BM=128, BN=128, BK=32, 256 threads, 3-stage
// cp.async, warp tile 32x64 (8 warps as 4m x 2n) -> 64 acc regs/thread,
// 2 CTAs/SM. Segmented-N for fused QKV; rmask: rna-round epilogue per seg.
// ---------------------------------------------------------------------------
#define BM 128
#define BN 128
#define BK 32
#define NCH (GK/BK)                // 64
#define RST 36
#define ATILEB (128*RST*4)         // 18432 B
#define STAGEB (2*ATILEB)          // 36864 B
#define GEMM_SMEM (3*STAGEB)       // 110592 B

__global__ __launch_bounds__(256, 2) void gemm_mma(
    const float* __restrict__ A,
    const float* __restrict__ B0, const float* __restrict__ B1,
    const float* __restrict__ B2,
    float* __restrict__ C0, float* __restrict__ C1, float* __restrict__ C2,
    int nb1, int nb2, int ld0, int rmask) {
    extern __shared__ float sm[];
    const int tid = threadIdx.x;
    const int bm = blockIdx.y * BM;
    const int bn = blockIdx.x * BN;
    const int wid = tid >> 5, lane = tid & 31;
    const int g = lane >> 2, tg = lane & 3;
    const int wm = (wid >> 1) * 32;      // 0,32,64,96
    const int wn = (wid & 1) * 64;       // 0,64

    const float* Bp; float* Cp; int nb, ldc, seg;
    if (bn < nb1)      { Bp = B0; Cp = C0; nb = bn;       ldc = ld0; seg = 0; }
    else if (bn < nb2) { Bp = B1; Cp = C1; nb = bn - nb1; ldc = 512; seg = 1; }
    else               { Bp = B2; Cp = C2; nb = bn - nb2; ldc = 512; seg = 2; }
    const bool rnd = (rmask >> seg) & 1;

    float c[2][8][4];
#pragma unroll
    for (int i = 0; i < 2; i++)
#pragma unroll
        for (int j = 0; j < 8; j++)
#pragma unroll
            for (int q = 0; q < 4; q++) c[i][j][q] = 0.f;

    const uint32_t sb = smem_u32(sm);

    auto load_chunk = [&](int kc, int s) {
        uint32_t base = sb + s * STAGEB;
#pragma unroll
        for (int j = 0; j < 8; j++) {
            int u = tid + j * 256;        // 0..2047
            uint32_t sa;
            const float* gp;
            if (u < 1024) {               // A: 128 rows x 8 float4
                int r = u >> 3, c16 = u & 7;
                sa = base + r * (RST*4) + c16 * 16;
                gp = A + (size_t)(bm + r) * GK + kc * BK + c16 * 4;
            } else {                      // B: 128 rows x 8 float4
                int uu = u - 1024;
                int r = uu >> 3, c16 = uu & 7;
                sa = base + ATILEB + r * (RST*4) + c16 * 16;
                gp = Bp + (size_t)(nb + r) * GK + kc * BK + c16 * 4;
            }
            asm volatile("cp.async.cg.shared.global [%0], [%1], 16;"
                         :: "r"(sa), "l"(gp));
        }
        asm volatile("cp.async.commit_group;" ::: "memory");
    };

    load_chunk(0, 0);
    load_chunk(1, 1);

    for (int t = 0; t < NCH; t++) {
        if (t + 2 < NCH) {
            load_chunk(t + 2, (t + 2) % 3);
            asm volatile("cp.async.wait_group 2;" ::: "memory");
        } else if (t + 1 < NCH) {
            asm volatile("cp.async.wait_group 1;" ::: "memory");
        } else {
            asm volatile("cp.async.wait_group 0;" ::: "memory");
        }
        __syncthreads();

        const float* Ab = sm + (t % 3) * (STAGEB/4);
        const float* Bb = Ab + ATILEB/4;
#pragma unroll
        for (int ks = 0; ks < 4; ks++) {
            const int k0 = ks * 8;
            uint32_t af[2][4], bf[8][2];
#pragma unroll
            for (int tm = 0; tm < 2; tm++) {
                const int m0 = wm + tm * 16;
                af[tm][0] = __float_as_uint(Ab[(m0 + g)     * RST + k0 + tg]);
                af[tm][1] = __float_as_uint(Ab[(m0 + g + 8) * RST + k0 + tg]);
                af[tm][2] = __float_as_uint(Ab[(m0 + g)     * RST + k0 + tg + 4]);
                af[tm][3] = __float_as_uint(Ab[(m0 + g + 8) * RST + k0 + tg + 4]);
            }
#pragma unroll
            for (int tn = 0; tn < 8; tn++) {
                const int n0 = wn + tn * 8;
                bf[tn][0] = __float_as_uint(Bb[(n0 + g) * RST + k0 + tg]);
                bf[tn][1] = __float_as_uint(Bb[(n0 + g) * RST + k0 + tg + 4]);
            }
#pragma unroll
            for (int tm = 0; tm < 2; tm++)
#pragma unroll
                for (int tn = 0; tn < 8; tn++)
                    mma_tf32(c[tm][tn], af[tm], bf[tn]);
        }
        __syncthreads();
    }

#pragma unroll
    for (int tm = 0; tm < 2; tm++) {
        const int row0 = bm + wm + tm * 16 + g;
#pragma unroll
        for (int tn = 0; tn < 8; tn++) {
            const int col = nb + wn + tn * 8 + tg * 2;
            float2 v0 = make_float2(c[tm][tn][0], c[tm][tn][1]);
            float2 v1 = make_float2(c[tm][tn][2], c[tm][tn][3]);
            if (rnd) {
                v0.x = rna(v0.x); v0.y = rna(v0.y);
                v1.x = rna(v1.x); v1.y = rna(v1.y);
            }
            *(float2*)&Cp[(size_t)row0 * ldc + col]       = v0;
            *(float2*)&Cp[(size_t)(row0 + 8) * ldc + col] = v1;
        }
    }
}

// ---------------------------------------------------------------------------
// Fused RoPE for q and k (in-place), writes tf32-rounded values
// ---------------------------------------------------------------------------
#define ROPE_TOT (BB*TT*(NH+NKV)*32)

__global__ void rope_fused(float* __restrict__ q, float* __restrict__ kk,
                           const float* __restrict__ cs, const float* __restrict__ sn) {
    int idx = blockIdx.x * blockDim.x + threadIdx.x;
    if (idx >= ROPE_TOT) return;
    int d  = idx & 31;
    int h  = (idx >> 5) % (NH + NKV);
    int bt = idx / (32 * (NH + NKV));
    int t  = bt & (TT - 1);
    float* row = (h < NH) ? q + (size_t)bt * QN + h * HD
                          : kk + (size_t)bt * KN + (h - NH) * HD;
    float x1 = row[d], x2 = row[d + 32];
    float c1 = cs[t * HD + d],      s1 = sn[t * HD + d];
    float c2 = cs[t * HD + d + 32], s2 = sn[t * HD + d + 32];
    row[d]      = rna(x1 * c1 - x2 * s1);
    row[d + 32] = rna(x2 * c2 + x1 * s2);
}

// ---------------------------------------------------------------------------
// Tensor-core flash attention v4: 256 threads (8 warps x 16 q-rows),
// q-tile 128, kv-tile 64, cp.async double-buffered K/V, 2 CTAs/SM.
// All inputs pre-rounded tf32. Smem: Kb[2][64][68], Vb[2][64][72],
// Ps[128][68] = 106496 B.
// ---------------------------------------------------------------------------
#define KST 68
#define VST 72
#define PST 68
#define ATTN_SMEM ((2*64*KST + 2*64*VST + 128*PST) * 4)

__global__ __launch_bounds__(256, 2) void attn_tc(const float* __restrict__ q,
                                                  const float* __restrict__ k,
                                                  const float* __restrict__ v,
                                                  float* __restrict__ o) {
    const int qt = (int)gridDim.x - 1 - (int)blockIdx.x;   // heavy CTAs first
    const int h  = blockIdx.y;
    const int b  = blockIdx.z;
    const int kvh = h >> 2;
    const int q0 = qt * 128;

    extern __shared__ float sm[];
    float* Kb = sm;                     // 2 x [64][KST]
    float* Vb = Kb + 2 * 64 * KST;      // 2 x [64][VST]
    float* Ps = Vb + 2 * 64 * VST;      // [128][PST] (Q staging, then P)

    const int tid = threadIdx.x;
    const int w = tid >> 5, lane = tid & 31;
    const int g = lane >> 2, tg = lane & 3;
    const int wq0 = w * 16;

    // ---- Stage all 128 Q rows into Ps (pre-rounded by rope) ----
#pragma unroll
    for (int j = 0; j < 8; j++) {
        int i = tid + j * 256;            // 0..2047 float4 units
        int r = i >> 4, c4 = i & 15;
        *(float4*)&Ps[r * PST + c4 * 4] =
            *(const float4*)&q[(size_t)(b * TT + q0 + r) * QN + h * HD + c4 * 4];
    }
    __syncthreads();

    uint32_t qf[8][4];
#pragma unroll
    for (int ks = 0; ks < 8; ks++) {
        const int k0 = ks * 8;
        qf[ks][0] = __float_as_uint(Ps[(wq0 + g)     * PST + k0 + tg]);
        qf[ks][1] = __float_as_uint(Ps[(wq0 + g + 8) * PST + k0 + tg]);
        qf[ks][2] = __float_as_uint(Ps[(wq0 + g)     * PST + k0 + tg + 4]);
        qf[ks][3] = __float_as_uint(Ps[(wq0 + g + 8) * PST + k0 + tg + 4]);
    }

    // cp.async one 64-row K/V tile into stage s
    auto cp_tile = [&](int kt, int s) {
        const float* kbp = k + (size_t)(b * TT + kt * 64) * KN + kvh * HD;
        const float* vbp = v + (size_t)(b * TT + kt * 64) * KN + kvh * HD;
        float* Kd = Kb + s * 64 * KST;
        float* Vd = Vb + s * 64 * VST;
#pragma unroll
        for (int j = 0; j < 8; j++) {
            int u = tid + j * 256;        // 0..2047
            int r = (u >> 4) & 63, c4 = u & 15;
            if (u < 1024) {
                uint32_t sa = smem_u32(&Kd[r * KST + c4 * 4]);
                asm volatile("cp.async.cg.shared.global [%0], [%1], 16;"
                             :: "r"(sa), "l"(kbp + (size_t)r * KN + c4 * 4));
            } else {
                uint32_t sa = smem_u32(&Vd[r * VST + c4 * 4]);
                asm volatile("cp.async.cg.shared.global [%0], [%1], 16;"
                             :: "r"(sa), "l"(vbp + (size_t)r * KN + c4 * 4));
            }
        }
        asm volatile("cp.async.commit_group;" ::: "memory");
    };

    float oacc[8][4];
#pragma unroll
    for (int nt = 0; nt < 8; nt++)
#pragma unroll
        for (int qq = 0; qq < 4; qq++) oacc[nt][qq] = 0.f;
    float m0 = -INFINITY, m1 = -INFINITY, l0 = 0.f, l1 = 0.f;

    const int nkt = 2 * qt + 2;
    cp_tile(0, 0);

    for (int kt = 0; kt < nkt; ++kt) {
        if (kt + 1 < nkt) {
            cp_tile(kt + 1, (kt + 1) & 1);
            asm volatile("cp.async.wait_group 1;" ::: "memory");
        } else {
            asm volatile("cp.async.wait_group 0;" ::: "memory");
        }
        __syncthreads();

        const float* Ks = Kb + (kt & 1) * 64 * KST;
        const float* Vs = Vb + (kt & 1) * 64 * VST;
        const int k0g = kt * 64;

        // ---- S = Q @ K^T ----
        float sc[8][4];
#pragma unroll
        for (int nt = 0; nt < 8; nt++)
#pragma unroll
            for (int qq = 0; qq < 4; qq++) sc[nt][qq] = 0.f;

#pragma unroll
        for (int ks = 0; ks < 8; ks++) {
            const int k0 = ks * 8;
            uint32_t bf[8][2];
#pragma unroll
            for (int nt = 0; nt < 8; nt++) {
                bf[nt][0] = __float_as_uint(Ks[(nt * 8 + g) * KST + k0 + tg]);
                bf[nt][1] = __float_as_uint(Ks[(nt * 8 + g) * KST + k0 + tg + 4]);
            }
#pragma unroll
            for (int nt = 0; nt < 8; nt++)
                mma_tf32(sc[nt], qf[ks], bf[nt]);
        }

        // ---- scale + causal mask ----
        const float scale = 0.125f;
        if (kt >= 2 * qt) {               // diagonal region
            const int r0 = q0 + wq0 + g, r1 = r0 + 8;
#pragma unroll
            for (int nt = 0; nt < 8; nt++) {
                int c0 = k0g + nt * 8 + 2 * tg, c1 = c0 + 1;
                sc[nt][0] = (c0 <= r0) ? sc[nt][0] * scale : -1e30f;
                sc[nt][1] = (c1 <= r0) ? sc[nt][1] * scale : -1e30f;
                sc[nt][2] = (c0 <= r1) ? sc[nt][2] * scale : -1e30f;
                sc[nt][3] = (c1 <= r1) ? sc[nt][3] * scale : -1e30f;
            }
        } else {
#pragma unroll
            for (int nt = 0; nt < 8; nt++)
#pragma unroll
                for (int qq = 0; qq < 4; qq++) sc[nt][qq] *= scale;
        }

        // ---- online softmax (rows g and g+8; reduce over tg lanes) ----
        float mx0 = -INFINITY, mx1 = -INFINITY;
#pragma unroll
        for (int nt = 0; nt < 8; nt++) {
            mx0 = fmaxf(mx0, fmaxf(sc[nt][0], sc[nt][1]));
            mx1 = fmaxf(mx1, fmaxf(sc[nt][2], sc[nt][3]));
        }
        mx0 = fmaxf(mx0, __shfl_xor_sync(0xffffffffu, mx0, 1));
        mx0 = fmaxf(mx0, __shfl_xor_sync(0xffffffffu, mx0, 2));
        mx1 = fmaxf(mx1, __shfl_xor_sync(0xffffffffu, mx1, 1));
        mx1 = fmaxf(mx1, __shfl_xor_sync(0xffffffffu, mx1, 2));

        float mn0 = fmaxf(m0, mx0), mn1 = fmaxf(m1, mx1);
        float al0 = __expf(m0 - mn0), al1 = __expf(m1 - mn1);
        m0 = mn0; m1 = mn1;
        float rs0 = 0.f, rs1 = 0.f;
#pragma unroll
        for (int nt = 0; nt < 8; nt++) {
            sc[nt][0] = __expf(sc[nt][0] - mn0);
            sc[nt][1] = __expf(sc[nt][1] - mn0);
            sc[nt][2] = __expf(sc[nt][2] - mn1);
            sc[nt][3] = __expf(sc[nt][3] - mn1);
            rs0 += sc[nt][0] + sc[nt][1];
            rs1 += sc[nt][2] + sc[nt][3];
        }
        rs0 += __shfl_xor_sync(0xffffffffu, rs0, 1);
        rs0 += __shfl_xor_sync(0xffffffffu, rs0, 2);
        rs1 += __shfl_xor_sync(0xffffffffu, rs1, 1);
        rs1 += __shfl_xor_sync(0xffffffffu, rs1, 2);
        l0 = l0 * al0 + rs0;
        l1 = l1 * al1 + rs1;
#pragma unroll
        for (int nt = 0; nt < 8; nt++) {
            oacc[nt][0] *= al0; oacc[nt][1] *= al0;
            oacc[nt][2] *= al1; oacc[nt][3] *= al1;
        }

        // ---- P to smem (warp-private rows), reload as A-frags ----
#pragma unroll
        for (int nt = 0; nt < 8; nt++) {
            *(float2*)&Ps[(wq0 + g)     * PST + nt * 8 + 2 * tg] =
                make_float2(sc[nt][0], sc[nt][1]);
            *(float2*)&Ps[(wq0 + g + 8) * PST + nt * 8 + 2 * tg] =
                make_float2(sc[nt][2], sc[nt][3]);
        }
        __syncwarp();

        // ---- O += P @ V ----
#pragma unroll
        for (int ks = 0; ks < 8; ks++) {
            const int kk = ks * 8;
            uint32_t af[4];
            af[0] = __float_as_uint(Ps[(wq0 + g)     * PST + kk + tg]);
            af[1] = __float_as_uint(Ps[(wq0 + g + 8) * PST + kk + tg]);
            af[2] = __float_as_uint(Ps[(wq0 + g)     * PST + kk + tg + 4]);
            af[3] = __float_as_uint(Ps[(wq0 + g + 8) * PST + kk + tg + 4]);
            uint32_t bf[8][2];
#pragma unroll
            for (int nt = 0; nt < 8; nt++) {
                bf[nt][0] = __float_as_uint(Vs[(kk + tg)     * VST + nt * 8 + g]);
                bf[nt][1] = __float_as_uint(Vs[(kk + tg + 4) * VST + nt * 8 + g]);
            }
#pragma unroll
            for (int nt = 0; nt < 8; nt++)
                mma_tf32(oacc[nt], af, bf[nt]);
        }
        __syncthreads();   // all warps done with this K/V buffer
    }

    // ---- normalize + write (tf32-rounded: feeds O-proj GEMM directly) ----
    const float inv0 = 1.f / l0, inv1 = 1.f / l1;
    const int rb = b * TT + q0 + wq0 + g;
#pragma unroll
    for (int nt = 0; nt < 8; nt++) {
        const int col = h * HD + nt * 8 + 2 * tg;
        *(float2*)&o[(size_t)rb * QN + col] =
            make_float2(rna(oacc[nt][0] * inv0), rna(oacc[nt][1] * inv0));
        *(float2*)&o[(size_t)(rb + 8) * QN + col] =
            make_float2(rna(oacc[nt][2] * inv1), rna(oacc[nt][3] * inv1));
    }
}

// ---------------------------------------------------------------------------
// Launcher
// ---------------------------------------------------------------------------
extern "C" void kernel_launch(void* const* d_in, const int* in_sizes, int n_in,
                              void* d_out, int out_size) {
    const float* x   = (const float*)d_in[0];
    const float* cs  = (const float*)d_in[1];
    const float* sn  = (const float*)d_in[2];
    const float* Wq  = (const float*)d_in[3];
    const float* Wk  = (const float*)d_in[4];
    const float* Wv  = (const float*)d_in[5];
    const float* Wo  = (const float*)d_in[6];
    float* out = (float*)d_out;

    float *q_ptr, *k_ptr, *v_ptr, *att_ptr;
    float *xc, *wqc, *wkc, *wvc, *woc;
    cudaGetSymbolAddress((void**)&q_ptr,  g_q);
    cudaGetSymbolAddress((void**)&k_ptr,  g_k);
    cudaGetSymbolAddress((void**)&v_ptr,  g_v);
    cudaGetSymbolAddress((void**)&att_ptr, g_att);
    cudaGetSymbolAddress((void**)&xc,   g_xc);
    cudaGetSymbolAddress((void**)&wqc,  g_wqc);
    cudaGetSymbolAddress((void**)&wkc,  g_wkc);
    cudaGetSymbolAddress((void**)&wvc,  g_wvc);
    cudaGetSymbolAddress((void**)&woc,  g_woc);

    cudaFuncSetAttribute(gemm_mma, cudaFuncAttributeMaxDynamicSharedMemorySize, GEMM_SMEM);
    cudaFuncSetAttribute(attn_tc,  cudaFuncAttributeMaxDynamicSharedMemorySize, ATTN_SMEM);

    // 1) Pre-round all GEMM operands (single launch)
    cvt_all<<<(N4_ALL + 255) / 256, 256>>>(x, Wq, Wk, Wv, Wo,
                                           xc, wqc, wkc, wvc, woc);

    // 2) Fused QKV projection: N = 2048 + 512 + 512; round V segment (bit 2)
    gemm_mma<<<dim3(3072/BN, MROWS/BM), 256, GEMM_SMEM>>>(
        xc, wqc, wkc, wvc, q_ptr, k_ptr, v_ptr, 2048, 2560, QN, 0b100);

    // 3) Fused RoPE on q and k (writes tf32-rounded)
    rope_fused<<<(ROPE_TOT + 255) / 256, 256>>>(q_ptr, k_ptr, cs, sn);

    // 4) Tensor-core flash attention (q-tile 128, 8 warps, double-buffered)
    attn_tc<<<dim3(TT / 128, NH, BB), 256, ATTN_SMEM>>>(q_ptr, k_ptr, v_ptr, att_ptr);

    // 5) Output projection (seg 0 only; no epilogue rounding)
    gemm_mma<<<dim3(DM/BN, MROWS/BM), 256, GEMM_SMEM>>>(
        att_ptr, woc, woc, woc, out, out, out, DM, DM + 512, DM, 0);
}